// round 1
// baseline (speedup 1.0000x reference)
#include <cuda_runtime.h>
#include <cstdint>

typedef unsigned long long u64;

// Problem constants
#define Bn   4
#define Cn   256
#define Hn   64
#define Wn   64
#define MIDn 64
#define ENCn 100   // = 4 (s*s) * 25 (k*k)

// -------- device scratch (no allocations allowed) --------
__device__ float g_feat[Bn * Hn * Wn * MIDn];   // NHWC: feat[((b*64+h)*64+w)*64 + m]
__device__ float g_wk[Bn * Hn * Wn * ENCn];     // softmaxed kernels: wk[pix*100 + p*25 + k]
__device__ u64   g_wp[MIDn * 9 * 50];           // packed enc weights: [(i*9+t)*50 + j] = (W[2j], W[2j+1])

// -------- f32x2 helpers (Blackwell packed fp32) --------
__device__ __forceinline__ u64 pack2(float lo, float hi) {
    u64 r; asm("mov.b64 %0, {%1, %2};" : "=l"(r) : "f"(lo), "f"(hi)); return r;
}
__device__ __forceinline__ void unpack2(u64 v, float& lo, float& hi) {
    asm("mov.b64 {%0, %1}, %2;" : "=f"(lo), "=f"(hi) : "l"(v));
}
__device__ __forceinline__ u64 fma2(u64 a, u64 b, u64 c) {  // d = a*b + c, lanewise f32x2
    u64 d; asm("fma.rn.f32x2 %0, %1, %2, %3;" : "=l"(d) : "l"(a), "l"(b), "l"(c)); return d;
}

// ============================================================
// K0: pack W_enc (100,64,3,3) -> g_wp[(i*9+t)*50+j] = (W[2j,i,t], W[2j+1,i,t])
// ============================================================
__global__ void k0_pack(const float* __restrict__ Wenc) {
    int e = blockIdx.x * 256 + threadIdx.x;
    if (e >= MIDn * 9 * 50) return;
    int j = e % 50;
    int t = (e / 50) % 9;
    int i = e / 450;
    int o0 = 2 * j;
    float a = Wenc[(size_t)o0 * 576 + i * 9 + t];
    float b = Wenc[(size_t)(o0 + 1) * 576 + i * 9 + t];
    g_wp[e] = pack2(a, b);
}

// ============================================================
// K1: feat = relu(W_comp @ x + b_comp), NHWC output
//   grid 128 blocks x 128 threads, 1 pixel/thread, 64 accumulators
//   W_comp transposed into smem ws[c*68 + m] (stride 68: float4-aligned)
// ============================================================
#define K1_SMEM ((256 * 68 + 64) * 4)

__global__ __launch_bounds__(128) void k1_compress(const float* __restrict__ x,
                                                   const float* __restrict__ Wc,
                                                   const float* __restrict__ bc) {
    extern __shared__ float sm1[];
    float* ws = sm1;              // [256][68] transposed weights
    float* bs = sm1 + 256 * 68;   // [64] bias
    int tid = threadIdx.x;

    for (int idx = tid; idx < 16384; idx += 128) {
        int m = idx >> 8, c = idx & 255;
        ws[c * 68 + m] = Wc[idx];          // coalesced read, transposed store
    }
    if (tid < 64) bs[tid] = bc[tid];
    __syncthreads();

    int pix = blockIdx.x * 128 + tid;      // 16384 pixels total
    int bb = pix >> 12;
    int hw = pix & 4095;
    const float* xp = x + ((size_t)bb << 20) + hw;  // b*256*4096 + hw

    float acc[64];
#pragma unroll
    for (int m = 0; m < 64; m++) acc[m] = 0.f;

    for (int c = 0; c < 256; c += 4) {
        float xv[4];
#pragma unroll
        for (int u = 0; u < 4; u++) xv[u] = __ldg(xp + (size_t)(c + u) * 4096);
#pragma unroll
        for (int u = 0; u < 4; u++) {
            const float4* wr = (const float4*)(ws + (c + u) * 68);
#pragma unroll
            for (int m4 = 0; m4 < 16; m4++) {
                float4 wv = wr[m4];
                acc[4 * m4 + 0] += xv[u] * wv.x;
                acc[4 * m4 + 1] += xv[u] * wv.y;
                acc[4 * m4 + 2] += xv[u] * wv.z;
                acc[4 * m4 + 3] += xv[u] * wv.w;
            }
        }
    }

    float4* fp = (float4*)(g_feat + ((size_t)pix << 6));
#pragma unroll
    for (int m4 = 0; m4 < 16; m4++) {
        float4 v;
        v.x = fmaxf(acc[4 * m4 + 0] + bs[4 * m4 + 0], 0.f);
        v.y = fmaxf(acc[4 * m4 + 1] + bs[4 * m4 + 1], 0.f);
        v.z = fmaxf(acc[4 * m4 + 2] + bs[4 * m4 + 2], 0.f);
        v.w = fmaxf(acc[4 * m4 + 3] + bs[4 * m4 + 3], 0.f);
        fp[m4] = v;
    }
}

// ============================================================
// K2: 3x3 conv (MID=64 -> ENC=100, SAME) + bias + softmax over 25 taps
//   grid 128 blocks x 128 threads; block = (batch, 2 rows x 64 cols), 1 pixel/thread
//   feat tile in smem as [i][row0..3][col0..65]; weights staged per 8-i chunk (packed f32x2)
//   100 fp32 accumulators per thread held as 50 packed f32x2
// ============================================================
#define K2_SMEM (3600 * 8 + 64 * 264 * 4)   // 28800B weights + 67584B feat tile

__global__ __launch_bounds__(128, 1) void k2_conv_softmax(const float* __restrict__ benc) {
    extern __shared__ char sm2[];
    u64* ws = (u64*)sm2;                        // [8i][9t][50j] packed weight pairs
    float* fs = (float*)(sm2 + 3600 * 8);       // [64i][4r][66c]

    int tid = threadIdx.x;
    int bb = blockIdx.x >> 5;
    int y0 = (blockIdx.x & 31) * 2;
    int ty = tid >> 6;        // 0..1
    int x = tid & 63;         // 0..63

    // Stage feat tile (rows y0-1 .. y0+2, cols -1 .. 64, zero padded)
    for (int pos = tid; pos < 264; pos += 128) {
        int r = pos / 66, cc = pos % 66;
        int iy = y0 + r - 1, ix = cc - 1;
        bool ok = ((unsigned)iy < 64u) && ((unsigned)ix < 64u);
        if (ok) {
            const float4* src = (const float4*)(g_feat + ((size_t)((bb * 64 + iy) * 64 + ix) << 6));
#pragma unroll
            for (int i0 = 0; i0 < 64; i0 += 4) {
                float4 v = src[i0 >> 2];
                fs[(i0 + 0) * 264 + pos] = v.x;
                fs[(i0 + 1) * 264 + pos] = v.y;
                fs[(i0 + 2) * 264 + pos] = v.z;
                fs[(i0 + 3) * 264 + pos] = v.w;
            }
        } else {
#pragma unroll
            for (int i0 = 0; i0 < 64; i0++) fs[i0 * 264 + pos] = 0.f;
        }
    }

    union Acc { u64 q[50]; float f[100]; } acc;
#pragma unroll
    for (int j = 0; j < 50; j++) acc.q[j] = 0ull;

    for (int chunk = 0; chunk < 8; chunk++) {
        __syncthreads();
        for (int e = tid; e < 3600; e += 128) ws[e] = g_wp[chunk * 3600 + e];
        __syncthreads();

#pragma unroll 1
        for (int ii = 0; ii < 8; ii++) {
            const float* frow = fs + (chunk * 8 + ii) * 264;
#pragma unroll
            for (int t = 0; t < 9; t++) {
                int dy = t / 3, dx = t % 3;
                float v = frow[(ty + dy) * 66 + x + dx];
                u64 v2 = pack2(v, v);
                const ulonglong2* wrow = (const ulonglong2*)(ws + (ii * 9 + t) * 50);
#pragma unroll
                for (int j2 = 0; j2 < 25; j2++) {
                    ulonglong2 ww = wrow[j2];
                    acc.q[2 * j2 + 0] = fma2(v2, ww.x, acc.q[2 * j2 + 0]);
                    acc.q[2 * j2 + 1] = fma2(v2, ww.y, acc.q[2 * j2 + 1]);
                }
            }
        }
    }

    // bias + softmax over k (groups of 25 within o = p*25 + k) + store
#pragma unroll
    for (int o = 0; o < 100; o++) acc.f[o] += __ldg(benc + o);

    int y = y0 + ty;
    float* dst = g_wk + (size_t)((bb * 64 + y) * 64 + x) * 100;
#pragma unroll
    for (int p = 0; p < 4; p++) {
        float mx = acc.f[p * 25];
#pragma unroll
        for (int k = 1; k < 25; k++) mx = fmaxf(mx, acc.f[p * 25 + k]);
        float s = 0.f;
#pragma unroll
        for (int k = 0; k < 25; k++) {
            float e = __expf(acc.f[p * 25 + k] - mx);
            acc.f[p * 25 + k] = e;
            s += e;
        }
        float inv = 1.f / s;
#pragma unroll
        for (int k = 0; k < 25; k++) dst[p * 25 + k] = acc.f[p * 25 + k] * inv;
    }
}

// ============================================================
// K3: content-aware gather + pixel rearrangement
//   out[b,c,h,w,p] = sum_k wk[pix, p*25+k] * x[b,c,h+k/5-2, w+k%5-2]
//   grid 256 blocks (b,h) x 256 threads (w,p). wk (packed x2) in registers;
//   x staged 4 channels/iter as two float2 smem rows with reg prefetch.
// ============================================================
__device__ __forceinline__ float xfetch(const float* __restrict__ x, int bb, int c, int h, int e) {
    int row = e / 68, col = e % 68;
    int iy = h + row - 2, ix = col - 2;
    if ((unsigned)iy >= 64u || (unsigned)ix >= 64u) return 0.f;
    return __ldg(x + (((size_t)(bb * 256 + c)) << 12) + (iy << 6) + ix);
}

__global__ __launch_bounds__(256) void k3_gather(const float* __restrict__ x,
                                                 float* __restrict__ out) {
    __shared__ float wk_s[6400];        // 64 pixels x 100
    __shared__ float2 xs01[340];        // 5 rows x 68 cols, channels (c0,c1)
    __shared__ float2 xs23[340];        // channels (c2,c3)

    int tid = threadIdx.x;
    int bb = blockIdx.x >> 6;
    int h = blockIdx.x & 63;
    int w = tid >> 2;   // 0..63
    int p = tid & 3;    // 0..3

    // stage wk row (64 pixels x 100 floats), coalesced float4
    {
        const float4* src = (const float4*)(g_wk + (size_t)(bb * 4096 + h * 64) * 100);
        float4* dst = (float4*)wk_s;
        for (int i = tid; i < 1600; i += 256) dst[i] = src[i];
    }

    // prefetch channels 0..3 into registers
    int e1 = tid;
    int e2 = tid + 256;
    bool has2 = (e2 < 340);
    float a0 = xfetch(x, bb, 0, h, e1), a1 = xfetch(x, bb, 1, h, e1);
    float a2 = xfetch(x, bb, 2, h, e1), a3 = xfetch(x, bb, 3, h, e1);
    float c0v = 0, c1v = 0, c2v = 0, c3v = 0;
    if (has2) {
        c0v = xfetch(x, bb, 0, h, e2); c1v = xfetch(x, bb, 1, h, e2);
        c2v = xfetch(x, bb, 2, h, e2); c3v = xfetch(x, bb, 3, h, e2);
    }
    __syncthreads();

    // load this thread's 25 softmaxed taps, packed (v,v)
    u64 wk2[25];
#pragma unroll
    for (int k = 0; k < 25; k++) {
        float v = wk_s[w * 100 + p * 25 + k];
        wk2[k] = pack2(v, v);
    }

    for (int it = 0; it < 64; it++) {
        __syncthreads();
        xs01[e1] = make_float2(a0, a1);
        xs23[e1] = make_float2(a2, a3);
        if (has2) {
            xs01[e2] = make_float2(c0v, c1v);
            xs23[e2] = make_float2(c2v, c3v);
        }
        if (it < 63) {  // prefetch next 4 channels (latency hidden by compute)
            int cb = (it + 1) * 4;
            a0 = xfetch(x, bb, cb + 0, h, e1); a1 = xfetch(x, bb, cb + 1, h, e1);
            a2 = xfetch(x, bb, cb + 2, h, e1); a3 = xfetch(x, bb, cb + 3, h, e1);
            if (has2) {
                c0v = xfetch(x, bb, cb + 0, h, e2); c1v = xfetch(x, bb, cb + 1, h, e2);
                c2v = xfetch(x, bb, cb + 2, h, e2); c3v = xfetch(x, bb, cb + 3, h, e2);
            }
        }
        __syncthreads();

        u64 acc01 = 0ull, acc23 = 0ull;
        const u64* q01 = (const u64*)xs01;
        const u64* q23 = (const u64*)xs23;
#pragma unroll
        for (int k = 0; k < 25; k++) {
            int off = (k / 5) * 68 + w + (k % 5);
            acc01 = fma2(q01[off], wk2[k], acc01);
            acc23 = fma2(q23[off], wk2[k], acc23);
        }
        float o0, o1, o2, o3;
        unpack2(acc01, o0, o1);
        unpack2(acc23, o2, o3);

        size_t ob = ((size_t)(bb * 256 + it * 4) * 4096 + (h << 6) + w) * 4 + p;
        out[ob + 0 * 16384] = o0;
        out[ob + 1 * 16384] = o1;
        out[ob + 2 * 16384] = o2;
        out[ob + 3 * 16384] = o3;
    }
}

// ============================================================
// launch
// ============================================================
extern "C" void kernel_launch(void* const* d_in, const int* in_sizes, int n_in,
                              void* d_out, int out_size) {
    (void)in_sizes; (void)n_in; (void)out_size;
    const float* x     = (const float*)d_in[0];
    const float* Wcomp = (const float*)d_in[1];
    const float* bcomp = (const float*)d_in[2];
    const float* Wenc  = (const float*)d_in[3];
    const float* benc  = (const float*)d_in[4];
    float* out = (float*)d_out;

    cudaFuncSetAttribute(k1_compress, cudaFuncAttributeMaxDynamicSharedMemorySize, K1_SMEM);
    cudaFuncSetAttribute(k2_conv_softmax, cudaFuncAttributeMaxDynamicSharedMemorySize, K2_SMEM);

    k0_pack<<<(MIDn * 9 * 50 + 255) / 256, 256>>>(Wenc);
    k1_compress<<<128, 128, K1_SMEM>>>(x, Wcomp, bcomp);
    k2_conv_softmax<<<128, 128, K2_SMEM>>>(benc);
    k3_gather<<<256, 256>>>(x, out);
}

// round 2
// speedup vs baseline: 1.3935x; 1.3935x over previous
#include <cuda_runtime.h>
#include <cstdint>

typedef unsigned long long u64;

// ---------- device scratch ----------
__device__ float g_feat[4 * 64 * 64 * 64];      // NHWC feat[pix][64]
__device__ float g_wk[4 * 64 * 64 * 100];       // softmaxed kernels
__device__ u64   g_wc2[2 * 256 * 16];           // k1 weights: [hf][c][16] pairs (m,m+1)
__device__ u64   g_wp2[64 * 9 * 4 * 14];        // k2 weights: [i][t][p][14] pairs (k,k+1), padded

// ---------- f32x2 helpers ----------
__device__ __forceinline__ u64 pack2(float lo, float hi) {
    u64 r; asm("mov.b64 %0, {%1, %2};" : "=l"(r) : "f"(lo), "f"(hi)); return r;
}
__device__ __forceinline__ void unpack2(u64 v, float& lo, float& hi) {
    asm("mov.b64 {%0, %1}, %2;" : "=f"(lo), "=f"(hi) : "l"(v));
}
__device__ __forceinline__ u64 fma2(u64 a, u64 b, u64 c) {
    u64 d; asm("fma.rn.f32x2 %0, %1, %2, %3;" : "=l"(d) : "l"(a), "l"(b), "l"(c)); return d;
}

// ============================================================
// K0: pack weights
//   g_wc2[hf][c][j] = (Wc[hf*32+2j, c], Wc[hf*32+2j+1, c])           (8192)
//   g_wp2[i][t][p][kp] = (We[p*25+2kp, i, t], We[p*25+2kp+1, i, t])  (32256, zero-padded)
// ============================================================
__global__ void k0_pack(const float* __restrict__ Wc, const float* __restrict__ We) {
    int e = blockIdx.x * 256 + threadIdx.x;
    if (e < 8192) {
        int j = e & 15, c = (e >> 4) & 255, hf = e >> 12;
        int m0 = hf * 32 + 2 * j;
        g_wc2[e] = pack2(Wc[(size_t)m0 * 256 + c], Wc[(size_t)(m0 + 1) * 256 + c]);
    } else if (e < 8192 + 32256) {
        int e2 = e - 8192;
        int kp = e2 % 14;
        int p  = (e2 / 14) & 3;
        int t  = (e2 / 56) % 9;
        int i  = e2 / 504;
        int o0 = p * 25 + 2 * kp;
        float lo = (2 * kp < 25)     ? We[(size_t)o0 * 576 + i * 9 + t] : 0.f;
        float hi = (2 * kp + 1 < 25) ? We[(size_t)(o0 + 1) * 576 + i * 9 + t] : 0.f;
        g_wp2[e2] = pack2(lo, hi);
    }
}

// ============================================================
// K1: feat = relu(Wc @ x + bc), NHWC output, f32x2
//   grid 256 (128 px-groups x 2 m-halves) x 128 threads, 1 px/thread, 16 u64 acc
// ============================================================
#define K1_SMEM (4096 * 8)

__global__ __launch_bounds__(128) void k1_compress(const float* __restrict__ x,
                                                   const float* __restrict__ bc) {
    extern __shared__ u64 ws[];      // [256][16] packed pairs for this half
    int tid = threadIdx.x;
    int hf  = blockIdx.x & 1;
    int pix = (blockIdx.x >> 1) * 128 + tid;

    const u64* src = g_wc2 + hf * 4096;
    for (int e = tid; e < 4096; e += 128) ws[e] = src[e];
    __syncthreads();

    int bb = pix >> 12, hw = pix & 4095;
    const float* xp = x + ((size_t)bb << 20) + hw;

    u64 acc[16];
#pragma unroll
    for (int j = 0; j < 16; j++) acc[j] = 0ull;

    for (int c = 0; c < 256; c += 4) {
        float xv[4];
#pragma unroll
        for (int u = 0; u < 4; u++) xv[u] = __ldg(xp + (size_t)(c + u) * 4096);
#pragma unroll
        for (int u = 0; u < 4; u++) {
            u64 v2 = pack2(xv[u], xv[u]);
            const ulonglong2* wr = (const ulonglong2*)(ws + (size_t)(c + u) * 16);
#pragma unroll
            for (int q = 0; q < 8; q++) {
                ulonglong2 ww = wr[q];
                acc[2 * q + 0] = fma2(v2, ww.x, acc[2 * q + 0]);
                acc[2 * q + 1] = fma2(v2, ww.y, acc[2 * q + 1]);
            }
        }
    }

    float* dst = g_feat + (size_t)pix * 64 + hf * 32;
#pragma unroll
    for (int q = 0; q < 8; q++) {
        float f0, f1, f2, f3;
        unpack2(acc[2 * q + 0], f0, f1);
        unpack2(acc[2 * q + 1], f2, f3);
        int m0 = hf * 32 + 4 * q;
        float4 v;
        v.x = fmaxf(f0 + __ldg(bc + m0 + 0), 0.f);
        v.y = fmaxf(f1 + __ldg(bc + m0 + 1), 0.f);
        v.z = fmaxf(f2 + __ldg(bc + m0 + 2), 0.f);
        v.w = fmaxf(f3 + __ldg(bc + m0 + 3), 0.f);
        ((float4*)dst)[q] = v;
    }
}

// ============================================================
// K2: 3x3 conv (64 -> 100) + bias + softmax over 25 taps
//   grid 256 (b, row) x 128 threads; thread = (px-pair, p); 2px x 25 outputs
//   feat tile (3 rows) in smem, weights chunked 8i; acc = 28 u64 (14 per px, padded)
// ============================================================
#define K2_FS_BYTES (64 * 200 * 4)               // 51200
#define K2_WQ_BYTES (4032 * 8)                   // 32256
#define K2_SMEM (K2_FS_BYTES + K2_WQ_BYTES)

__global__ __launch_bounds__(128) void k2_conv_softmax(const float* __restrict__ benc) {
    extern __shared__ char sm2[];
    float* fs = (float*)sm2;                     // [64 i][200] (3 rows x 66 cols, pad)
    u64* wq = (u64*)(sm2 + K2_FS_BYTES);         // [8 ii][9 t][4 p][14]

    int tid = threadIdx.x;
    int bb = blockIdx.x >> 6;
    int y  = blockIdx.x & 63;
    int xp = tid & 31;        // pixel pair: cols 2xp, 2xp+1
    int p  = tid >> 5;        // 0..3 (one warp per p)

    // stage feat rows y-1..y+1, cols -1..64 (198 positions)
    for (int pos = tid; pos < 198; pos += 128) {
        int r = pos / 66, cc = pos % 66;
        int iy = y + r - 1, ix = cc - 1;
        if (((unsigned)iy < 64u) && ((unsigned)ix < 64u)) {
            const float4* s4 = (const float4*)(g_feat + ((size_t)((bb * 64 + iy) * 64 + ix) << 6));
#pragma unroll
            for (int i0 = 0; i0 < 64; i0 += 4) {
                float4 v = s4[i0 >> 2];
                fs[(i0 + 0) * 200 + pos] = v.x;
                fs[(i0 + 1) * 200 + pos] = v.y;
                fs[(i0 + 2) * 200 + pos] = v.z;
                fs[(i0 + 3) * 200 + pos] = v.w;
            }
        } else {
#pragma unroll
            for (int i0 = 0; i0 < 64; i0++) fs[i0 * 200 + pos] = 0.f;
        }
    }

    u64 acc[28];              // [px(2)][14]
#pragma unroll
    for (int j = 0; j < 28; j++) acc[j] = 0ull;

    for (int chunk = 0; chunk < 8; chunk++) {
        __syncthreads();
        for (int e = tid; e < 4032; e += 128) wq[e] = g_wp2[chunk * 4032 + e];
        __syncthreads();

#pragma unroll 1
        for (int ii = 0; ii < 8; ii++) {
            const float* fr = fs + (chunk * 8 + ii) * 200;
            float win[3][4];
#pragma unroll
            for (int dy = 0; dy < 3; dy++) {
                const float2* rp = (const float2*)(fr + dy * 66 + 2 * xp);
                float2 a = rp[0], b = rp[1];
                win[dy][0] = a.x; win[dy][1] = a.y; win[dy][2] = b.x; win[dy][3] = b.y;
            }
#pragma unroll
            for (int t = 0; t < 9; t++) {
                int dy = t / 3, dx = t % 3;
                u64 v0 = pack2(win[dy][dx], win[dy][dx]);
                u64 v1 = pack2(win[dy][dx + 1], win[dy][dx + 1]);
                const ulonglong2* wr = (const ulonglong2*)(wq + (size_t)((ii * 9 + t) * 4 + p) * 14);
#pragma unroll
                for (int q = 0; q < 7; q++) {
                    ulonglong2 ww = wr[q];
                    acc[2 * q + 0]      = fma2(v0, ww.x, acc[2 * q + 0]);
                    acc[2 * q + 1]      = fma2(v0, ww.y, acc[2 * q + 1]);
                    acc[14 + 2 * q + 0] = fma2(v1, ww.x, acc[14 + 2 * q + 0]);
                    acc[14 + 2 * q + 1] = fma2(v1, ww.y, acc[14 + 2 * q + 1]);
                }
            }
        }
    }

    // bias + softmax + store, per pixel of the pair
#pragma unroll
    for (int px = 0; px < 2; px++) {
        float l[25];
#pragma unroll
        for (int kp = 0; kp < 13; kp++) {
            float lo, hi;
            unpack2(acc[px * 14 + kp], lo, hi);
            l[2 * kp] = lo;
            if (2 * kp + 1 < 25) l[2 * kp + 1] = hi;
        }
        float mx = -1e30f;
#pragma unroll
        for (int k = 0; k < 25; k++) {
            l[k] += __ldg(benc + p * 25 + k);
            mx = fmaxf(mx, l[k]);
        }
        float s = 0.f;
#pragma unroll
        for (int k = 0; k < 25; k++) {
            float e = __expf(l[k] - mx);
            l[k] = e;
            s += e;
        }
        float inv = 1.f / s;
        float* dst = g_wk + (size_t)((bb * 64 + y) * 64 + 2 * xp + px) * 100 + p * 25;
#pragma unroll
        for (int k = 0; k < 25; k++) dst[k] = l[k] * inv;
    }
}

// ============================================================
// K3: content-aware gather, 4 channels/round (float4), double-buffered (1 BAR/round)
//   grid 256 (b,h) x 256 threads (w x p); wk taps in registers
// ============================================================
__device__ __forceinline__ float4 fetch4(const float* __restrict__ x, int bb, int c, int h, int e) {
    int row = e / 68, col = e % 68;
    int iy = h + row - 2, ix = col - 2;
    float4 v = make_float4(0.f, 0.f, 0.f, 0.f);
    if ((unsigned)iy < 64u && (unsigned)ix < 64u) {
        const float* b = x + (((size_t)(bb * 256 + c)) << 12) + (iy << 6) + ix;
        v.x = __ldg(b);
        v.y = __ldg(b + 4096);
        v.z = __ldg(b + 8192);
        v.w = __ldg(b + 12288);
    }
    return v;
}

__global__ __launch_bounds__(256) void k3_gather(const float* __restrict__ x,
                                                 float* __restrict__ out) {
    __shared__ float wk_s[6400];          // 64 px x 100
    __shared__ float4 xs[2][340];         // 5 rows x 68 cols, 4 channels each

    int tid = threadIdx.x;
    int bb = blockIdx.x >> 6;
    int h = blockIdx.x & 63;
    int w = tid >> 2;
    int p = tid & 3;

    // stage wk row
    {
        const float4* src = (const float4*)(g_wk + (size_t)(bb * 4096 + h * 64) * 100);
        float4* dst = (float4*)wk_s;
        for (int i = tid; i < 1600; i += 256) dst[i] = src[i];
    }

    int e1 = tid;
    int e2 = tid + 256;
    bool has2 = (e2 < 340);

    // channel group 0 into buffer 0
    float4 pf1 = fetch4(x, bb, 0, h, e1);
    float4 pf2 = has2 ? fetch4(x, bb, 0, h, e2) : make_float4(0, 0, 0, 0);
    xs[0][e1] = pf1;
    if (has2) xs[0][e2] = pf2;
    __syncthreads();

    u64 wk2[25];
#pragma unroll
    for (int k = 0; k < 25; k++) {
        float v = wk_s[w * 100 + p * 25 + k];
        wk2[k] = pack2(v, v);
    }

    size_t obase = ((size_t)(bb * 256) * 4096 + (h << 6) + w) * 4 + p;

    for (int it = 0; it < 64; it++) {
        int cur = it & 1;
        if (it < 63) {
            pf1 = fetch4(x, bb, (it + 1) * 4, h, e1);
            if (has2) pf2 = fetch4(x, bb, (it + 1) * 4, h, e2);
        }

        u64 a01 = 0ull, a23 = 0ull;
        const ulonglong2* q = (const ulonglong2*)xs[cur];
#pragma unroll
        for (int k = 0; k < 25; k++) {
            int off = (k / 5) * 68 + w + (k % 5);
            ulonglong2 v = q[off];
            a01 = fma2(v.x, wk2[k], a01);
            a23 = fma2(v.y, wk2[k], a23);
        }

        if (it < 63) {
            xs[cur ^ 1][e1] = pf1;
            if (has2) xs[cur ^ 1][e2] = pf2;
        }

        float o0, o1, o2, o3;
        unpack2(a01, o0, o1);
        unpack2(a23, o2, o3);
        size_t ob = obase + (size_t)it * 4 * 16384;
        out[ob + 0 * 16384] = o0;
        out[ob + 1 * 16384] = o1;
        out[ob + 2 * 16384] = o2;
        out[ob + 3 * 16384] = o3;

        __syncthreads();
    }
}

// ============================================================
// launch
// ============================================================
extern "C" void kernel_launch(void* const* d_in, const int* in_sizes, int n_in,
                              void* d_out, int out_size) {
    (void)in_sizes; (void)n_in; (void)out_size;
    const float* x     = (const float*)d_in[0];
    const float* Wcomp = (const float*)d_in[1];
    const float* bcomp = (const float*)d_in[2];
    const float* Wenc  = (const float*)d_in[3];
    const float* benc  = (const float*)d_in[4];
    float* out = (float*)d_out;

    cudaFuncSetAttribute(k1_compress, cudaFuncAttributeMaxDynamicSharedMemorySize, K1_SMEM);
    cudaFuncSetAttribute(k2_conv_softmax, cudaFuncAttributeMaxDynamicSharedMemorySize, K2_SMEM);

    k0_pack<<<(8192 + 32256 + 255) / 256, 256>>>(Wcomp, Wenc);
    k1_compress<<<256, 128, K1_SMEM>>>(x, bcomp);
    k2_conv_softmax<<<256, 128, K2_SMEM>>>(benc);
    k3_gather<<<256, 256>>>(x, out);
}